// round 3
// baseline (speedup 1.0000x reference)
#include <cuda_runtime.h>
#include <cuda_bf16.h>
#include <cstdint>

// RBF_Conv2d: x (16,1,256,256) f32, w (64,1,5,5) f32 -> out (16,64,252,252) f32
// out[b,o,h,w] = exp(-0.5 * d2 / var_hw),  d = sqrt(max(||patch-w||^2,1e-12))
// var_hw = sample var (ddof=1) of dist over the (B*O)=1024 matrix at pixel (h,w)

#define B_  16
#define O_  64
#define HO  252
#define WO  252
#define WT  6       // w-pixels per block (252 = 42*6)
#define WIN 12      // window cols staged (WT + 4 needed, padded to 12 for float4)

__device__ __forceinline__ float ex2_approx(float a) {
    float r;
    asm("ex2.approx.ftz.f32 %0, %1;" : "=f"(r) : "f"(a));
    return r;
}
__device__ __forceinline__ float rsqrt_approx(float a) {
    float r;
    asm("rsqrt.approx.ftz.f32 %0, %1;" : "=f"(r) : "f"(a));
    return r;
}

__global__ __launch_bounds__(512, 2)
void rbf_conv2d_kernel(const float* __restrict__ x,
                       const float* __restrict__ w,
                       float* __restrict__ out)
{
    __shared__ float xs[B_][5][WIN];     // x window: 16 b x 5 rows x 12 cols
    __shared__ float ws[25][O_];         // weights transposed: [k][o]
    __shared__ float pns[B_][WT];        // patch norms per (b, w)
    __shared__ float red[16][WT];        // per-warp partial sums
    __shared__ float mean_s[WT];
    __shared__ float cinv_s[WT];

    const int tid = threadIdx.x;
    const int h   = blockIdx.y;
    const int w0  = blockIdx.x * WT;

    // ---- load weights transposed: ws[k][o] = w[o*25+k] ----
    for (int i = tid; i < 25 * O_; i += 512) {
        int k = i >> 6, o = i & 63;
        ws[k][o] = w[o * 25 + k];
    }
    // ---- load x window: rows h..h+4, cols w0..w0+11 (clamp: only w0..w0+9 used) ----
    for (int i = tid; i < B_ * 5 * WIN; i += 512) {
        int b = i / (5 * WIN);
        int r = (i / WIN) % 5;
        int c = i % WIN;
        int col = w0 + c; if (col > 255) col = 255;   // pad cols never read
        xs[b][r][c] = x[b * 65536 + (h + r) * 256 + col];
    }
    __syncthreads();

    // ---- patch norms pn[b][wi] ----
    if (tid < B_ * WT) {
        int b = tid / WT, wi = tid % WT;
        float s = 0.f;
        #pragma unroll
        for (int kh = 0; kh < 5; kh++)
            #pragma unroll
            for (int kw = 0; kw < 5; kw++) {
                float v = xs[b][kh][wi + kw];
                s = fmaf(v, v, s);
            }
        pns[b][wi] = s;
    }
    __syncthreads();

    // ---- thread tile: 2 b x 1 o x 6 w ----
    const int ot = tid & 63;        // o index (lanes stride-1 -> conflict-free LDS)
    const int bt = tid >> 6;        // 0..7 (constant within warp -> broadcast LDS)
    const int b0 = bt * 2;

    float acc[2][WT];
    #pragma unroll
    for (int i = 0; i < 2; i++)
        #pragma unroll
        for (int wi = 0; wi < WT; wi++) acc[i][wi] = 0.f;
    float wn = 0.f;

    #pragma unroll
    for (int kh = 0; kh < 5; kh++) {
        float win0[WIN], win1[WIN];
        #pragma unroll
        for (int c = 0; c < WIN; c += 4) {
            float4 a = *(const float4*)&xs[b0][kh][c];
            win0[c] = a.x; win0[c+1] = a.y; win0[c+2] = a.z; win0[c+3] = a.w;
            float4 bq = *(const float4*)&xs[b0 + 1][kh][c];
            win1[c] = bq.x; win1[c+1] = bq.y; win1[c+2] = bq.z; win1[c+3] = bq.w;
        }
        float wr[5];
        #pragma unroll
        for (int t = 0; t < 5; t++) wr[t] = ws[kh * 5 + t][ot];
        #pragma unroll
        for (int kw = 0; kw < 5; kw++) {
            float wv = wr[kw];
            wn = fmaf(wv, wv, wn);
            #pragma unroll
            for (int wi = 0; wi < WT; wi++) {
                acc[0][wi] = fmaf(win0[wi + kw], wv, acc[0][wi]);
                acc[1][wi] = fmaf(win1[wi + kw], wv, acc[1][wi]);
            }
        }
    }

    // ---- dist = d2 * rsqrt(d2); pass-1 local sums ----
    float sums[WT];
    #pragma unroll
    for (int wi = 0; wi < WT; wi++) sums[wi] = 0.f;

    #pragma unroll
    for (int i = 0; i < 2; i++)
        #pragma unroll
        for (int wi = 0; wi < WT; wi++) {
            float d2 = pns[b0 + i][wi] + wn - 2.f * acc[i][wi];
            d2 = fmaxf(d2, 1e-12f);
            float d = d2 * rsqrt_approx(d2);
            acc[i][wi] = d;
            sums[wi] += d;
        }

    const int warp = tid >> 5;
    const int lane = tid & 31;

    // ---- pass 1: mean over 1024 values per w ----
    #pragma unroll
    for (int off = 16; off; off >>= 1)
        #pragma unroll
        for (int wi = 0; wi < WT; wi++)
            sums[wi] += __shfl_xor_sync(0xffffffffu, sums[wi], off);
    if (lane == 0) {
        #pragma unroll
        for (int wi = 0; wi < WT; wi++) red[warp][wi] = sums[wi];
    }
    __syncthreads();
    if (tid < WT) {
        float s = 0.f;
        #pragma unroll
        for (int r = 0; r < 16; r++) s += red[r][tid];
        mean_s[tid] = s * (1.0f / 1024.0f);
    }
    __syncthreads();

    // ---- pass 2: sum (d - mean)^2 ----
    float mloc[WT];
    #pragma unroll
    for (int wi = 0; wi < WT; wi++) { mloc[wi] = mean_s[wi]; sums[wi] = 0.f; }
    #pragma unroll
    for (int i = 0; i < 2; i++)
        #pragma unroll
        for (int wi = 0; wi < WT; wi++) {
            float dd = acc[i][wi] - mloc[wi];
            sums[wi] = fmaf(dd, dd, sums[wi]);
        }
    #pragma unroll
    for (int off = 16; off; off >>= 1)
        #pragma unroll
        for (int wi = 0; wi < WT; wi++)
            sums[wi] += __shfl_xor_sync(0xffffffffu, sums[wi], off);
    if (lane == 0) {
        #pragma unroll
        for (int wi = 0; wi < WT; wi++) red[warp][wi] = sums[wi];
    }
    __syncthreads();
    if (tid < WT) {
        float s = 0.f;
        #pragma unroll
        for (int r = 0; r < 16; r++) s += red[r][tid];
        float var = s * (1.0f / 1023.0f);
        // exp(-0.5*d^2/var) = exp2( d^2 * (-0.5*log2(e)/var) )
        cinv_s[tid] = -0.72134752044448170368f / var;
    }
    __syncthreads();

    float cl[WT];
    #pragma unroll
    for (int wi = 0; wi < WT; wi++) cl[wi] = cinv_s[wi];

    // ---- write out: per (b,o) 6 contiguous floats (8B-aligned float2 x3) ----
    #pragma unroll
    for (int i = 0; i < 2; i++) {
        size_t base = ((size_t)((b0 + i) * O_ + ot) * HO + h) * WO + w0;
        #pragma unroll
        for (int g = 0; g < WT; g += 2) {
            float d0 = acc[i][g + 0];
            float d1 = acc[i][g + 1];
            float2 v;
            v.x = ex2_approx(cl[g + 0] * d0 * d0);
            v.y = ex2_approx(cl[g + 1] * d1 * d1);
            *(float2*)&out[base + g] = v;
        }
    }
}

extern "C" void kernel_launch(void* const* d_in, const int* in_sizes, int n_in,
                              void* d_out, int out_size)
{
    const float* x = (const float*)d_in[0];      // (16,1,256,256)
    const float* w = (const float*)d_in[1];      // (64,1,5,5)
    float* out = (float*)d_out;                  // (16,64,252,252)

    dim3 grid(WO / WT, HO);                      // (42, 252)
    rbf_conv2d_kernel<<<grid, 512>>>(x, w, out);
}

// round 4
// speedup vs baseline: 1.3357x; 1.3357x over previous
#include <cuda_runtime.h>
#include <cuda_bf16.h>
#include <cstdint>

// RBF_Conv2d: x (16,1,256,256) f32, w (64,1,5,5) f32 -> out (16,64,252,252) f32
// out[b,o,h,w] = exp(-0.5 * d^2 / var_hw),  d = sqrt(max(||patch-w||^2,1e-12))
// var_hw = sample var (ddof=1) of d over the (B*O)=1024 matrix at pixel (h,w)

#define B_  16
#define O_  64
#define HO  252
#define WO  252
#define WT  12      // w-pixels per block (252 = 21*12)
#define WIN 16      // window cols staged (WT + 4, padded to 16)

__device__ __forceinline__ float ex2_approx(float a) {
    float r; asm("ex2.approx.ftz.f32 %0, %1;" : "=f"(r) : "f"(a)); return r;
}
__device__ __forceinline__ float rsqrt_approx(float a) {
    float r; asm("rsqrt.approx.ftz.f32 %0, %1;" : "=f"(r) : "f"(a)); return r;
}

__global__ __launch_bounds__(512, 2)
void rbf_conv2d_kernel(const float* __restrict__ x,
                       const float* __restrict__ w,
                       float* __restrict__ out)
{
    __shared__ float xs[B_][5][WIN];     // x window: 16 b x 5 rows x 16 cols
    __shared__ float ws[25][O_];         // weights transposed: [k][o]
    __shared__ float pns[B_][WT];        // patch norms per (b, w)
    __shared__ float red[16][WT];        // per-warp partial sums
    __shared__ float mean_s[WT];
    __shared__ float cinv_s[WT];

    const int tid  = threadIdx.x;
    const int h    = blockIdx.y;
    const int w0   = blockIdx.x * WT;
    const int lane = tid & 31;
    const int warp = tid >> 5;           // 0..15 == batch index b (warp-uniform)

    // ---- load weights transposed: ws[k][o] = w[o*25+k] ----
    for (int i = tid; i < 25 * O_; i += 512) {
        int k = i >> 6, o = i & 63;
        ws[k][o] = w[o * 25 + k];
    }
    // ---- load x window: rows h..h+4, cols w0..w0+15 (in-bounds: 240+15=255) ----
    for (int i = tid; i < B_ * 5 * WIN; i += 512) {
        int b = i / (5 * WIN);
        int r = (i / WIN) % 5;
        int c = i & (WIN - 1);
        xs[b][r][c] = x[b * 65536 + (h + r) * 256 + (w0 + c)];
    }
    __syncthreads();

    // ---- patch norms pn[b][wi] ----
    if (tid < B_ * WT) {
        int b = tid / WT, wi = tid % WT;
        float s = 0.f;
        #pragma unroll
        for (int kh = 0; kh < 5; kh++)
            #pragma unroll
            for (int kw = 0; kw < 5; kw++) {
                float v = xs[b][kh][wi + kw];
                s = fmaf(v, v, s);
            }
        pns[b][wi] = s;
    }
    __syncthreads();

    // ---- thread tile: 1 b x 2 o x 12 w ----
    const int b  = warp;                 // warp-uniform -> xs reads are broadcast
    const int o0 = lane * 2;             // consecutive lanes -> conflict-free LDS.64

    float acc[2][WT];
    #pragma unroll
    for (int j = 0; j < 2; j++)
        #pragma unroll
        for (int wi = 0; wi < WT; wi++) acc[j][wi] = 0.f;
    float wn0 = 0.f, wn1 = 0.f;

    #pragma unroll
    for (int kh = 0; kh < 5; kh++) {
        float win[WIN];
        #pragma unroll
        for (int c = 0; c < WIN; c += 4) {
            float4 a = *(const float4*)&xs[b][kh][c];
            win[c] = a.x; win[c+1] = a.y; win[c+2] = a.z; win[c+3] = a.w;
        }
        #pragma unroll
        for (int kw = 0; kw < 5; kw++) {
            float2 wv = *(const float2*)&ws[kh * 5 + kw][o0];
            wn0 = fmaf(wv.x, wv.x, wn0);
            wn1 = fmaf(wv.y, wv.y, wn1);
            #pragma unroll
            for (int wi = 0; wi < WT; wi++) {
                float p = win[wi + kw];
                acc[0][wi] = fmaf(p, wv.x, acc[0][wi]);
                acc[1][wi] = fmaf(p, wv.y, acc[1][wi]);
            }
        }
    }

    // ---- dist = d2 * rsqrt(d2); pass-1 local sums ----
    float sums[WT];
    #pragma unroll
    for (int wi = 0; wi < WT; wi++) sums[wi] = 0.f;
    #pragma unroll
    for (int j = 0; j < 2; j++) {
        const float wn = j ? wn1 : wn0;
        #pragma unroll
        for (int wi = 0; wi < WT; wi++) {
            float d2 = pns[b][wi] + wn - 2.f * acc[j][wi];
            d2 = fmaxf(d2, 1e-12f);
            float d = d2 * rsqrt_approx(d2);
            acc[j][wi] = d;
            sums[wi] += d;
        }
    }

    // ---- pass 1: mean over 1024 values per w ----
    #pragma unroll
    for (int off = 16; off; off >>= 1)
        #pragma unroll
        for (int wi = 0; wi < WT; wi++)
            sums[wi] += __shfl_xor_sync(0xffffffffu, sums[wi], off);
    if (lane == 0) {
        #pragma unroll
        for (int wi = 0; wi < WT; wi++) red[warp][wi] = sums[wi];
    }
    __syncthreads();
    if (tid < WT) {
        float s = 0.f;
        #pragma unroll
        for (int r = 0; r < 16; r++) s += red[r][tid];
        mean_s[tid] = s * (1.0f / 1024.0f);
    }
    __syncthreads();

    // ---- pass 2: sum (d - mean)^2 ----
    float mloc[WT];
    #pragma unroll
    for (int wi = 0; wi < WT; wi++) { mloc[wi] = mean_s[wi]; sums[wi] = 0.f; }
    #pragma unroll
    for (int j = 0; j < 2; j++)
        #pragma unroll
        for (int wi = 0; wi < WT; wi++) {
            float dd = acc[j][wi] - mloc[wi];
            sums[wi] = fmaf(dd, dd, sums[wi]);
        }
    #pragma unroll
    for (int off = 16; off; off >>= 1)
        #pragma unroll
        for (int wi = 0; wi < WT; wi++)
            sums[wi] += __shfl_xor_sync(0xffffffffu, sums[wi], off);
    if (lane == 0) {
        #pragma unroll
        for (int wi = 0; wi < WT; wi++) red[warp][wi] = sums[wi];
    }
    __syncthreads();
    if (tid < WT) {
        float s = 0.f;
        #pragma unroll
        for (int r = 0; r < 16; r++) s += red[r][tid];
        float var = s * (1.0f / 1023.0f);
        // exp(-0.5*d^2/var) = exp2( d^2 * (-0.5*log2(e)/var) )
        cinv_s[tid] = -0.72134752044448170368f / var;
    }
    __syncthreads();

    float cl[WT];
    #pragma unroll
    for (int wi = 0; wi < WT; wi++) cl[wi] = cinv_s[wi];

    // ---- write out: per (b,o) 12 contiguous floats (16B-aligned float4 x3) ----
    #pragma unroll
    for (int j = 0; j < 2; j++) {
        size_t base = ((size_t)(b * O_ + (o0 + j)) * HO + h) * WO + w0;
        #pragma unroll
        for (int g = 0; g < WT; g += 4) {
            float d0 = acc[j][g + 0];
            float d1 = acc[j][g + 1];
            float d2v = acc[j][g + 2];
            float d3 = acc[j][g + 3];
            float4 v;
            v.x = ex2_approx(cl[g + 0] * d0 * d0);
            v.y = ex2_approx(cl[g + 1] * d1 * d1);
            v.z = ex2_approx(cl[g + 2] * d2v * d2v);
            v.w = ex2_approx(cl[g + 3] * d3 * d3);
            *(float4*)&out[base + g] = v;
        }
    }
}

extern "C" void kernel_launch(void* const* d_in, const int* in_sizes, int n_in,
                              void* d_out, int out_size)
{
    const float* x = (const float*)d_in[0];      // (16,1,256,256)
    const float* w = (const float*)d_in[1];      // (64,1,5,5)
    float* out = (float*)d_out;                  // (16,64,252,252)

    dim3 grid(WO / WT, HO);                      // (21, 252)
    rbf_conv2d_kernel<<<grid, 512>>>(x, w, out);
}

// round 6
// speedup vs baseline: 1.5124x; 1.1322x over previous
#include <cuda_runtime.h>
#include <cuda_bf16.h>
#include <cstdint>

// RBF_Conv2d: x (16,1,256,256) f32, w (64,1,5,5) f32 -> out (16,64,252,252) f32
// out[b,o,h,w] = exp(-0.5 * d^2 / var_hw),  d = sqrt(max(||patch-w||^2,1e-12))
// var_hw = sample var (ddof=1) of d over the (B*O)=1024 matrix at pixel (h,w)

#define B_  16
#define O_  64
#define HO  252
#define WO  252
#define WT  12      // w-pixels per block (252 = 21*12)
#define WIN 16      // window cols staged (WT + 4, padded to 16)
#define NQ  6       // WT/2 packed pairs

typedef unsigned long long u64;

__device__ __forceinline__ u64 fma2(u64 a, u64 b, u64 c) {
    u64 d; asm("fma.rn.f32x2 %0, %1, %2, %3;" : "=l"(d) : "l"(a), "l"(b), "l"(c)); return d;
}
__device__ __forceinline__ u64 add2(u64 a, u64 b) {
    u64 d; asm("add.rn.f32x2 %0, %1, %2;" : "=l"(d) : "l"(a), "l"(b)); return d;
}
__device__ __forceinline__ u64 pack2(float lo, float hi) {
    u64 d; asm("mov.b64 %0, {%1, %2};" : "=l"(d) : "f"(lo), "f"(hi)); return d;
}
__device__ __forceinline__ void unpack2(u64 v, float& lo, float& hi) {
    asm("mov.b64 {%0, %1}, %2;" : "=f"(lo), "=f"(hi) : "l"(v));
}
__device__ __forceinline__ float ex2_approx(float a) {
    float r; asm("ex2.approx.ftz.f32 %0, %1;" : "=f"(r) : "f"(a)); return r;
}
__device__ __forceinline__ float sqrt_approx(float a) {
    float r; asm("sqrt.approx.ftz.f32 %0, %1;" : "=f"(r) : "f"(a)); return r;
}

__global__ __launch_bounds__(512, 2)
void rbf_conv2d_kernel(const float* __restrict__ x,
                       const float* __restrict__ w,
                       float* __restrict__ out)
{
    __shared__ __align__(16) float xs [B_][5][WIN];  // window cols w0..w0+15
    __shared__ __align__(16) float xss[B_][5][WIN];  // shifted copy: col w0+1+c
    __shared__ __align__(16) float ws [25][O_];      // weights transposed [k][o]
    __shared__ __align__(16) float pns[B_][WT];      // patch norms
    __shared__ float red[16][WT];
    __shared__ float mean_s[WT];
    __shared__ float cinv_s[WT];

    const int tid  = threadIdx.x;
    const int h    = blockIdx.y;
    const int w0   = blockIdx.x * WT;
    const int lane = tid & 31;
    const int warp = tid >> 5;           // == batch index b (warp-uniform)

    // ---- weights transposed ----
    for (int i = tid; i < 25 * O_; i += 512) {
        int k = i >> 6, o = i & 63;
        ws[k][o] = w[o * 25 + k];
    }
    // ---- x window + shifted copy ----
    for (int i = tid; i < B_ * 5 * WIN; i += 512) {
        int b = i / (5 * WIN);
        int r = (i / WIN) % 5;
        int c = i & (WIN - 1);
        float v = x[b * 65536 + (h + r) * 256 + (w0 + c)];   // w0+c <= 240+15=255
        xs[b][r][c] = v;
        if (c > 0) xss[b][r][c - 1] = v;
        if (c == WIN - 1) xss[b][r][c] = v;                  // pad, never read
    }
    __syncthreads();

    // ---- patch norms ----
    if (tid < B_ * WT) {
        int b = tid / WT, wi = tid % WT;
        float s = 0.f;
        #pragma unroll
        for (int kh = 0; kh < 5; kh++)
            #pragma unroll
            for (int kw = 0; kw < 5; kw++) {
                float v = xs[b][kh][wi + kw];
                s = fmaf(v, v, s);
            }
        pns[b][wi] = s;
    }
    __syncthreads();

    // ---- thread tile: 1 b x 2 o x 12 w (as 6 packed pairs) ----
    const int b  = warp;                 // warp-uniform -> broadcast LDS
    const int o0 = lane * 2;

    u64 acc0[NQ], acc1[NQ];
    #pragma unroll
    for (int q = 0; q < NQ; q++) { acc0[q] = 0ull; acc1[q] = 0ull; }
    float wn0 = 0.f, wn1 = 0.f;

    #pragma unroll
    for (int kh = 0; kh < 5; kh++) {
        const u64* we = (const u64*)&xs [b][kh][0];   // 8 aligned pairs
        const u64* wo = (const u64*)&xss[b][kh][0];   // 8 shifted pairs
        u64 ev[8];
        #pragma unroll
        for (int p = 0; p < 8; p++) ev[p] = we[p];
        #pragma unroll
        for (int kw = 0; kw < 5; kw++) {
            float2 wv = *(const float2*)&ws[kh * 5 + kw][o0];
            wn0 = fmaf(wv.x, wv.x, wn0);
            wn1 = fmaf(wv.y, wv.y, wn1);
            u64 wp0 = pack2(wv.x, wv.x);
            u64 wp1 = pack2(wv.y, wv.y);
            if ((kw & 1) == 0) {
                const int s = kw >> 1;
                #pragma unroll
                for (int q = 0; q < NQ; q++) {
                    u64 m = ev[q + s];
                    acc0[q] = fma2(m, wp0, acc0[q]);
                    acc1[q] = fma2(m, wp1, acc1[q]);
                }
            } else {
                const int s = (kw - 1) >> 1;
                #pragma unroll
                for (int q = 0; q < NQ; q++) {
                    u64 m = wo[q + s];                // broadcast LDS.64
                    acc0[q] = fma2(m, wp0, acc0[q]);
                    acc1[q] = fma2(m, wp1, acc1[q]);
                }
            }
        }
    }

    // ---- d = sqrt(max(pn + wn - 2*cross, 1e-12)); pass-1 local sums ----
    float dist[2][WT];
    float sums[WT];
    #pragma unroll
    for (int wi = 0; wi < WT; wi++) sums[wi] = 0.f;

    const u64 m2 = pack2(-2.f, -2.f);
    const u64* pnp = (const u64*)&pns[b][0];
    #pragma unroll
    for (int j = 0; j < 2; j++) {
        const float wn = j ? wn1 : wn0;
        const u64 wnp = pack2(wn, wn);
        #pragma unroll
        for (int q = 0; q < NQ; q++) {
            u64 d2p = fma2(j ? acc1[q] : acc0[q], m2, add2(pnp[q], wnp));
            float a, bb;
            unpack2(d2p, a, bb);
            a  = fmaxf(a,  1e-12f);
            bb = fmaxf(bb, 1e-12f);
            float da = sqrt_approx(a);
            float db = sqrt_approx(bb);
            dist[j][2 * q]     = da;
            dist[j][2 * q + 1] = db;
            sums[2 * q]     += da;
            sums[2 * q + 1] += db;
        }
    }

    // ---- pass 1: mean over 1024 values per w (shfl butterfly + cross-warp) ----
    #pragma unroll
    for (int off = 16; off; off >>= 1)
        #pragma unroll
        for (int wi = 0; wi < WT; wi++)
            sums[wi] += __shfl_xor_sync(0xffffffffu, sums[wi], off);
    if (lane == 0) {
        #pragma unroll
        for (int wi = 0; wi < WT; wi++) red[warp][wi] = sums[wi];
    }
    __syncthreads();
    if (tid < WT) {
        float s = 0.f;
        #pragma unroll
        for (int r = 0; r < 16; r++) s += red[r][tid];
        mean_s[tid] = s * (1.0f / 1024.0f);
    }
    __syncthreads();

    // ---- pass 2: sum (d - mean)^2 ----
    float mloc[WT];
    #pragma unroll
    for (int wi = 0; wi < WT; wi++) { mloc[wi] = mean_s[wi]; sums[wi] = 0.f; }
    #pragma unroll
    for (int j = 0; j < 2; j++)
        #pragma unroll
        for (int wi = 0; wi < WT; wi++) {
            float dd = dist[j][wi] - mloc[wi];
            sums[wi] = fmaf(dd, dd, sums[wi]);
        }
    #pragma unroll
    for (int off = 16; off; off >>= 1)
        #pragma unroll
        for (int wi = 0; wi < WT; wi++)
            sums[wi] += __shfl_xor_sync(0xffffffffu, sums[wi], off);
    if (lane == 0) {
        #pragma unroll
        for (int wi = 0; wi < WT; wi++) red[warp][wi] = sums[wi];
    }
    __syncthreads();
    if (tid < WT) {
        float s = 0.f;
        #pragma unroll
        for (int r = 0; r < 16; r++) s += red[r][tid];
        float var = s * (1.0f / 1023.0f);
        // exp(-0.5*d^2/var) = exp2( d^2 * (-0.5*log2(e)/var) )
        cinv_s[tid] = -0.72134752044448170368f / var;
    }
    __syncthreads();

    float cl[WT];
    #pragma unroll
    for (int wi = 0; wi < WT; wi++) cl[wi] = cinv_s[wi];

    // ---- write out: per (b,o) 12 contiguous floats (float4 x3) ----
    #pragma unroll
    for (int j = 0; j < 2; j++) {
        size_t base = ((size_t)(b * O_ + (o0 + j)) * HO + h) * WO + w0;
        #pragma unroll
        for (int g = 0; g < WT; g += 4) {
            float d0 = dist[j][g + 0];
            float d1 = dist[j][g + 1];
            float d2v = dist[j][g + 2];
            float d3 = dist[j][g + 3];
            float4 v;
            v.x = ex2_approx(cl[g + 0] * d0 * d0);
            v.y = ex2_approx(cl[g + 1] * d1 * d1);
            v.z = ex2_approx(cl[g + 2] * d2v * d2v);
            v.w = ex2_approx(cl[g + 3] * d3 * d3);
            *(float4*)&out[base + g] = v;
        }
    }
}

extern "C" void kernel_launch(void* const* d_in, const int* in_sizes, int n_in,
                              void* d_out, int out_size)
{
    const float* x = (const float*)d_in[0];      // (16,1,256,256)
    const float* w = (const float*)d_in[1];      // (64,1,5,5)
    float* out = (float*)d_out;                  // (16,64,252,252)

    dim3 grid(WO / WT, HO);                      // (21, 252)
    rbf_conv2d_kernel<<<grid, 512>>>(x, w, out);
}

// round 7
// speedup vs baseline: 1.5130x; 1.0004x over previous
#include <cuda_runtime.h>
#include <cuda_bf16.h>
#include <cstdint>

// RBF_Conv2d: x (16,1,256,256) f32, w (64,1,5,5) f32 -> out (16,64,252,252) f32
// out[b,o,h,w] = exp(-0.5 * d^2 / var_hw),  d = sqrt(max(||patch-w||^2,1e-12))
// var_hw = sample var (ddof=1) of d over the (B*O)=1024 matrix at pixel (h,w)

#define B_  16
#define O_  64
#define HO  252
#define WO  252
#define WT  12      // w-pixels per block (252 = 21*12)
#define WIN 16      // window cols staged (WT + 4, padded to 16)
#define NQ  6       // WT/2 packed pairs

typedef unsigned long long u64;

__device__ __forceinline__ u64 fma2(u64 a, u64 b, u64 c) {
    u64 d; asm("fma.rn.f32x2 %0, %1, %2, %3;" : "=l"(d) : "l"(a), "l"(b), "l"(c)); return d;
}
__device__ __forceinline__ u64 add2(u64 a, u64 b) {
    u64 d; asm("add.rn.f32x2 %0, %1, %2;" : "=l"(d) : "l"(a), "l"(b)); return d;
}
__device__ __forceinline__ u64 pack2(float lo, float hi) {
    u64 d; asm("mov.b64 %0, {%1, %2};" : "=l"(d) : "f"(lo), "f"(hi)); return d;
}
__device__ __forceinline__ void unpack2(u64 v, float& lo, float& hi) {
    asm("mov.b64 {%0, %1}, %2;" : "=f"(lo), "=f"(hi) : "l"(v));
}
// odd-aligned pair {hi(a), lo(b)} built in registers (ALU pipe, no LDS)
__device__ __forceinline__ u64 mkodd(u64 a, u64 b) {
    u64 r;
    asm("{\n\t"
        ".reg .b32 alo, ahi, blo, bhi;\n\t"
        "mov.b64 {alo, ahi}, %1;\n\t"
        "mov.b64 {blo, bhi}, %2;\n\t"
        "mov.b64 %0, {ahi, blo};\n\t"
        "}" : "=l"(r) : "l"(a), "l"(b));
    return r;
}
__device__ __forceinline__ float ex2_approx(float a) {
    float r; asm("ex2.approx.ftz.f32 %0, %1;" : "=f"(r) : "f"(a)); return r;
}
__device__ __forceinline__ float sqrt_approx(float a) {
    float r; asm("sqrt.approx.ftz.f32 %0, %1;" : "=f"(r) : "f"(a)); return r;
}

__global__ __launch_bounds__(512, 2)
void rbf_conv2d_kernel(const float* __restrict__ x,
                       const float* __restrict__ w,
                       float* __restrict__ out)
{
    __shared__ __align__(16) float xs [B_][5][WIN];  // window cols w0..w0+15
    __shared__ __align__(16) float ws [25][O_];      // weights transposed [k][o]
    __shared__ __align__(16) float wns[O_];          // wn[o] = sum_k w[o][k]^2
    __shared__ __align__(16) float pns[B_][WT];      // patch norms
    __shared__ float red[16][WT];
    __shared__ float mean_s[WT];
    __shared__ float cinv_s[WT];

    const int tid  = threadIdx.x;
    const int h    = blockIdx.y;
    const int w0   = blockIdx.x * WT;
    const int lane = tid & 31;
    const int warp = tid >> 5;           // == batch index b (warp-uniform)

    // ---- weights transposed ----
    for (int i = tid; i < 25 * O_; i += 512) {
        int k = i >> 6, o = i & 63;
        ws[k][o] = w[o * 25 + k];
    }
    // ---- x window ----
    for (int i = tid; i < B_ * 5 * WIN; i += 512) {
        int b = i / (5 * WIN);
        int r = (i / WIN) % 5;
        int c = i & (WIN - 1);
        xs[b][r][c] = x[b * 65536 + (h + r) * 256 + (w0 + c)];  // w0+c <= 255
    }
    __syncthreads();

    // ---- weight norms (64 threads) + patch norms (192 threads) ----
    if (tid < O_) {
        float s = 0.f;
        #pragma unroll
        for (int k = 0; k < 25; k++) {
            float v = ws[k][tid];
            s = fmaf(v, v, s);
        }
        wns[tid] = s;
    } else if (tid >= 64 && tid < 64 + B_ * WT) {
        int t = tid - 64;
        int b = t / WT, wi = t % WT;
        float s = 0.f;
        #pragma unroll
        for (int kh = 0; kh < 5; kh++)
            #pragma unroll
            for (int kw = 0; kw < 5; kw++) {
                float v = xs[b][kh][wi + kw];
                s = fmaf(v, v, s);
            }
        pns[b][wi] = s;
    }
    __syncthreads();

    // ---- thread tile: 1 b x 2 o x 12 w (6 packed pairs) ----
    const int b  = warp;                 // warp-uniform -> broadcast LDS
    const int o0 = lane * 2;

    u64 acc0[NQ], acc1[NQ];
    #pragma unroll
    for (int q = 0; q < NQ; q++) { acc0[q] = 0ull; acc1[q] = 0ull; }

    #pragma unroll
    for (int kh = 0; kh < 5; kh++) {
        // 8 even pairs via 4x LDS.128 (warp-broadcast)
        u64 ev[8];
        {
            const uint4* p = (const uint4*)&xs[b][kh][0];
            #pragma unroll
            for (int t = 0; t < 4; t++) {
                uint4 v = p[t];
                ev[2 * t]     = (u64)v.x | ((u64)v.y << 32);
                ev[2 * t + 1] = (u64)v.z | ((u64)v.w << 32);
            }
        }
        // 7 odd pairs in registers (ALU)
        u64 od[7];
        #pragma unroll
        for (int i = 0; i < 7; i++) od[i] = mkodd(ev[i], ev[i + 1]);

        #pragma unroll
        for (int kw = 0; kw < 5; kw++) {
            float2 wv = *(const float2*)&ws[kh * 5 + kw][o0];
            u64 wp0 = pack2(wv.x, wv.x);
            u64 wp1 = pack2(wv.y, wv.y);
            #pragma unroll
            for (int q = 0; q < NQ; q++) {
                u64 m = ((kw & 1) == 0) ? ev[q + (kw >> 1)] : od[q + ((kw - 1) >> 1)];
                acc0[q] = fma2(m, wp0, acc0[q]);
                acc1[q] = fma2(m, wp1, acc1[q]);
            }
        }
    }

    // ---- d = sqrt(max(pn + wn - 2*cross, 1e-12)); pass-1 local sums ----
    float2 wnv = *(const float2*)&wns[o0];
    float dist[2][WT];
    float sums[WT];
    #pragma unroll
    for (int wi = 0; wi < WT; wi++) sums[wi] = 0.f;

    const u64 m2 = pack2(-2.f, -2.f);
    const u64* pnp = (const u64*)&pns[b][0];
    #pragma unroll
    for (int j = 0; j < 2; j++) {
        const float wn = j ? wnv.y : wnv.x;
        const u64 wnp = pack2(wn, wn);
        #pragma unroll
        for (int q = 0; q < NQ; q++) {
            u64 d2p = fma2(j ? acc1[q] : acc0[q], m2, add2(pnp[q], wnp));
            float a, bb;
            unpack2(d2p, a, bb);
            a  = fmaxf(a,  1e-12f);
            bb = fmaxf(bb, 1e-12f);
            float da = sqrt_approx(a);
            float db = sqrt_approx(bb);
            dist[j][2 * q]     = da;
            dist[j][2 * q + 1] = db;
            sums[2 * q]     += da;
            sums[2 * q + 1] += db;
        }
    }

    // ---- pass 1: mean over 1024 values per w ----
    #pragma unroll
    for (int off = 16; off; off >>= 1)
        #pragma unroll
        for (int wi = 0; wi < WT; wi++)
            sums[wi] += __shfl_xor_sync(0xffffffffu, sums[wi], off);
    if (lane == 0) {
        #pragma unroll
        for (int wi = 0; wi < WT; wi++) red[warp][wi] = sums[wi];
    }
    __syncthreads();
    if (tid < WT) {
        float s = 0.f;
        #pragma unroll
        for (int r = 0; r < 16; r++) s += red[r][tid];
        mean_s[tid] = s * (1.0f / 1024.0f);
    }
    __syncthreads();

    // ---- pass 2: sum (d - mean)^2 ----
    float mloc[WT];
    #pragma unroll
    for (int wi = 0; wi < WT; wi++) { mloc[wi] = mean_s[wi]; sums[wi] = 0.f; }
    #pragma unroll
    for (int j = 0; j < 2; j++)
        #pragma unroll
        for (int wi = 0; wi < WT; wi++) {
            float dd = dist[j][wi] - mloc[wi];
            sums[wi] = fmaf(dd, dd, sums[wi]);
        }
    #pragma unroll
    for (int off = 16; off; off >>= 1)
        #pragma unroll
        for (int wi = 0; wi < WT; wi++)
            sums[wi] += __shfl_xor_sync(0xffffffffu, sums[wi], off);
    if (lane == 0) {
        #pragma unroll
        for (int wi = 0; wi < WT; wi++) red[warp][wi] = sums[wi];
    }
    __syncthreads();
    if (tid < WT) {
        float s = 0.f;
        #pragma unroll
        for (int r = 0; r < 16; r++) s += red[r][tid];
        float var = s * (1.0f / 1023.0f);
        // exp(-0.5*d^2/var) = exp2( d^2 * (-0.5*log2(e)/var) )
        cinv_s[tid] = -0.72134752044448170368f / var;
    }
    __syncthreads();

    float cl[WT];
    #pragma unroll
    for (int wi = 0; wi < WT; wi++) cl[wi] = cinv_s[wi];

    // ---- write out: per (b,o) 12 contiguous floats (float4 x3) ----
    #pragma unroll
    for (int j = 0; j < 2; j++) {
        size_t base = ((size_t)(b * O_ + (o0 + j)) * HO + h) * WO + w0;
        #pragma unroll
        for (int g = 0; g < WT; g += 4) {
            float d0 = dist[j][g + 0];
            float d1 = dist[j][g + 1];
            float d2v = dist[j][g + 2];
            float d3 = dist[j][g + 3];
            float4 v;
            v.x = ex2_approx(cl[g + 0] * d0 * d0);
            v.y = ex2_approx(cl[g + 1] * d1 * d1);
            v.z = ex2_approx(cl[g + 2] * d2v * d2v);
            v.w = ex2_approx(cl[g + 3] * d3 * d3);
            *(float4*)&out[base + g] = v;
        }
    }
}

extern "C" void kernel_launch(void* const* d_in, const int* in_sizes, int n_in,
                              void* d_out, int out_size)
{
    const float* x = (const float*)d_in[0];      // (16,1,256,256)
    const float* w = (const float*)d_in[1];      // (64,1,5,5)
    float* out = (float*)d_out;                  // (16,64,252,252)

    dim3 grid(WO / WT, HO);                      // (21, 252)
    rbf_conv2d_kernel<<<grid, 512>>>(x, w, out);
}